// round 2
// baseline (speedup 1.0000x reference)
#include <cuda_runtime.h>
#include <math.h>

// DiscreteBayesianFlow: probs = softmax( beta*(K*onehot(x)-1) + sqrt(beta) * noise @ L0^T )
// with C0 = (K+0.001) I - 11^T equicorrelated  =>  Cholesky column k is constant c_k below
// the diagonal, d_k on it:
//   c_k = -sqrt(alpha / ((alpha-k)(alpha-k-1)))
//   d_k =  sqrt(alpha (alpha-k-1) / (alpha-k))      (alpha = K + 0.001, fp32-rounded)
// => (noise @ L0^T)_j = prefix_{k<j}(c_k n_k) + d_j n_j  — an O(K) exclusive scan per row.
// Kernel = streaming scan + softmax: ~32 MB traffic, memory-bound.

#define KC 256
#define ROWS_PER_BLOCK 8
#define NTHREADS (ROWS_PER_BLOCK * 32)

static __device__ __forceinline__ float warp_max(float v) {
#pragma unroll
    for (int off = 16; off > 0; off >>= 1)
        v = fmaxf(v, __shfl_xor_sync(0xffffffffu, v, off));
    return v;
}

static __device__ __forceinline__ float warp_sum(float v) {
#pragma unroll
    for (int off = 16; off > 0; off >>= 1)
        v += __shfl_xor_sync(0xffffffffu, v, off);
    return v;
}

__global__ __launch_bounds__(NTHREADS)
void dbf_kernel(const int* __restrict__ data,
                const float* __restrict__ t,
                const float* __restrict__ noise,
                float* __restrict__ out,
                int n_rows)
{
    __shared__ float s_c[KC];
    __shared__ float s_d[KC];

    const int tid  = threadIdx.x;
    const int lane = tid & 31;
    const int warp = tid >> 5;

    // Closed-form Cholesky table, once per block (double kills the
    // cancellation in the last columns; alpha is the fp32-rounded 256.001
    // so the constant matches the reference's fp32 C0 exactly).
    {
        const double alpha = (double)256.001f;
        double f  = alpha - (double)tid;      // alpha - j
        double fm = f - 1.0;                  // alpha - j - 1
        double rs = 1.0 / sqrt(f * fm);
        double sa = sqrt(alpha);
        s_c[tid] = (float)(-sa * rs);         // c_j
        s_d[tid] = (float)( sa * fm * rs);    // d_j = sqrt(alpha*fm/f)
    }
    __syncthreads();

    const int row = blockIdx.x * ROWS_PER_BLOCK + warp;
    if (row >= n_rows) return;

    // Issue both 16B noise loads first (MLP=2), then scalars.
    const float4* nrow = (const float4*)(noise + (size_t)row * KC);
    const float4 nA = nrow[lane];
    const float4 nB = nrow[32 + lane];

    const float tv = t[row];     // broadcast (all lanes same addr)
    const int   x  = data[row];

    float sb = fminf(tv, 1.0f - 1e-6f);       // sqrt_beta (MAX_SQRT_BETA = 1)
    const bool lo = (sb < 1e-10f);            // tested BEFORE min-clip, like the ref
    sb = fmaxf(sb, 1e-10f);
    const float beta = sb * sb;

    const float4 cA = ((const float4*)s_c)[lane];
    const float4 cB = ((const float4*)s_c)[32 + lane];
    const float4 dA = ((const float4*)s_d)[lane];
    const float4 dB = ((const float4*)s_d)[32 + lane];

    // Weighted scan terms: w_k = c_k * n_k
    const float wA0 = cA.x * nA.x, wA1 = cA.y * nA.y, wA2 = cA.z * nA.z, wA3 = cA.w * nA.w;
    const float wB0 = cB.x * nB.x, wB1 = cB.y * nB.y, wB2 = cB.z * nB.z, wB3 = cB.w * nB.w;

    const float sA = (wA0 + wA1) + (wA2 + wA3);
    const float sB = (wB0 + wB1) + (wB2 + wB3);

    // Two interleaved Kogge-Stone inclusive scans (independent chains overlap).
    float vA = sA, vB = sB;
#pragma unroll
    for (int off = 1; off < 32; off <<= 1) {
        float uA = __shfl_up_sync(0xffffffffu, vA, off);
        float uB = __shfl_up_sync(0xffffffffu, vB, off);
        if (lane >= off) { vA += uA; vB += uB; }
    }
    const float exclA = vA - sA;
    const float totA  = __shfl_sync(0xffffffffu, vA, 31);
    const float exclB = totA + vB - sB;

    // y_k = prefix_k + d_k*n_k ;  logit_k = sb*y_k - beta + (k==x)*beta*K
    const float bonus = beta * (float)KC;
    float lg[8];
    {
        float p = exclA;
        const int k = 4 * lane;
        lg[0] = fmaf(sb, p + dA.x * nA.x, -beta) + ((k + 0 == x) ? bonus : 0.0f); p += wA0;
        lg[1] = fmaf(sb, p + dA.y * nA.y, -beta) + ((k + 1 == x) ? bonus : 0.0f); p += wA1;
        lg[2] = fmaf(sb, p + dA.z * nA.z, -beta) + ((k + 2 == x) ? bonus : 0.0f); p += wA2;
        lg[3] = fmaf(sb, p + dA.w * nA.w, -beta) + ((k + 3 == x) ? bonus : 0.0f);
    }
    {
        float p = exclB;
        const int k = 128 + 4 * lane;
        lg[4] = fmaf(sb, p + dB.x * nB.x, -beta) + ((k + 0 == x) ? bonus : 0.0f); p += wB0;
        lg[5] = fmaf(sb, p + dB.y * nB.y, -beta) + ((k + 1 == x) ? bonus : 0.0f); p += wB1;
        lg[6] = fmaf(sb, p + dB.z * nB.z, -beta) + ((k + 2 == x) ? bonus : 0.0f); p += wB2;
        lg[7] = fmaf(sb, p + dB.w * nB.w, -beta) + ((k + 3 == x) ? bonus : 0.0f);
    }

    // Warp-wide softmax over the 256 logits.
    float m = fmaxf(fmaxf(fmaxf(lg[0], lg[1]), fmaxf(lg[2], lg[3])),
                    fmaxf(fmaxf(lg[4], lg[5]), fmaxf(lg[6], lg[7])));
    m = warp_max(m);

    float e[8];
    float s = 0.0f;
#pragma unroll
    for (int i = 0; i < 8; i++) { e[i] = __expf(lg[i] - m); s += e[i]; }
    s = warp_sum(s);
    const float inv = __frcp_rn(s);

    float4 oA, oB;
    if (lo) {                                  // warp-uniform branch
        const float uni = 1.0f / (float)KC;
        oA = make_float4(uni, uni, uni, uni);
        oB = oA;
    } else {
        oA = make_float4(e[0] * inv, e[1] * inv, e[2] * inv, e[3] * inv);
        oB = make_float4(e[4] * inv, e[5] * inv, e[6] * inv, e[7] * inv);
    }

    float4* orow = (float4*)(out + (size_t)row * KC);
    orow[lane]      = oA;
    orow[32 + lane] = oB;
}

extern "C" void kernel_launch(void* const* d_in, const int* in_sizes, int n_in,
                              void* d_out, int out_size)
{
    const int*   data  = (const int*)  d_in[0];   // [B,S] int32 class indices
    const float* t     = (const float*)d_in[1];   // [B,S] float32
    const float* noise = (const float*)d_in[2];   // [B,S,K] float32
    float*       out   = (float*)d_out;           // [B,S,K] float32

    const int n_rows = in_sizes[0];               // B*S
    const int blocks = (n_rows + ROWS_PER_BLOCK - 1) / ROWS_PER_BLOCK;
    dbf_kernel<<<blocks, NTHREADS>>>(data, t, noise, out, n_rows);
}

// round 3
// speedup vs baseline: 2.7351x; 2.7351x over previous
#include <cuda_runtime.h>
#include <math.h>

// DiscreteBayesianFlow: probs = softmax( beta*(K*onehot(x)-1) + sqrt(beta) * noise @ L0^T )
// with C0 = (K+0.001) I - 11^T equicorrelated  =>  Cholesky column k is constant c_k below
// the diagonal, d_k on it (alpha = fp32(256.001)):
//   c_k = -sqrt(alpha / ((alpha-k)(alpha-k-1)))
//   d_k =  sqrt(alpha (alpha-k-1) / (alpha-k))
// => (noise @ L0^T)_j = prefix_{k<j}(c_k n_k) + d_j n_j  — an O(K) exclusive scan per row.
//
// R2 lesson: the table init MUST NOT use fp64 — 2048 blocks x fp64 sqrt sequences
// saturated the ~2 FP64-op/cyc/SM pipe and dominated the whole kernel (29 us).
// The closed form has no cancellation, so fp32 (MUFU) init is accurate to ~1e-6.

#define KC 256
#define ROWS_PER_BLOCK 8
#define NTHREADS (ROWS_PER_BLOCK * 32)

static __device__ __forceinline__ float warp_max(float v) {
#pragma unroll
    for (int off = 16; off > 0; off >>= 1)
        v = fmaxf(v, __shfl_xor_sync(0xffffffffu, v, off));
    return v;
}

static __device__ __forceinline__ float warp_sum(float v) {
#pragma unroll
    for (int off = 16; off > 0; off >>= 1)
        v += __shfl_xor_sync(0xffffffffu, v, off);
    return v;
}

__global__ __launch_bounds__(NTHREADS)
void dbf_kernel(const int* __restrict__ data,
                const float* __restrict__ t,
                const float* __restrict__ noise,
                float* __restrict__ out,
                int n_rows)
{
    __shared__ float s_c[KC];
    __shared__ float s_d[KC];

    const int tid  = threadIdx.x;
    const int lane = tid & 31;
    const int warp = tid >> 5;

    // Closed-form Cholesky table, once per block, PURE FP32 (2 sqrtf + 2 div
    // per thread; ~100 cyc/block instead of the fp64 disaster).
    {
        const float alpha = 256.001f;                 // fp32-rounded K+0.001
        const float f  = alpha - (float)tid;          // alpha - j   (exact-ish)
        const float fm = f - 1.0f;                    // alpha - j - 1
        s_c[tid] = -sqrtf(__fdividef(alpha, f * fm)); // c_j
        s_d[tid] =  sqrtf(__fdividef(alpha * fm, f)); // d_j
    }
    __syncthreads();

    const int row = blockIdx.x * ROWS_PER_BLOCK + warp;
    if (row >= n_rows) return;

    // Issue both 16B noise loads first (MLP=2), then scalars.
    const float4* nrow = (const float4*)(noise + (size_t)row * KC);
    const float4 nA = nrow[lane];
    const float4 nB = nrow[32 + lane];

    const float tv = t[row];     // broadcast (all lanes same addr)
    const int   x  = data[row];

    float sb = fminf(tv, 1.0f - 1e-6f);       // sqrt_beta (MAX_SQRT_BETA = 1)
    const bool lo = (sb < 1e-10f);            // tested BEFORE min-clip, like the ref
    sb = fmaxf(sb, 1e-10f);
    const float beta = sb * sb;

    const float4 cA = ((const float4*)s_c)[lane];
    const float4 cB = ((const float4*)s_c)[32 + lane];
    const float4 dA = ((const float4*)s_d)[lane];
    const float4 dB = ((const float4*)s_d)[32 + lane];

    // Weighted scan terms: w_k = c_k * n_k
    const float wA0 = cA.x * nA.x, wA1 = cA.y * nA.y, wA2 = cA.z * nA.z, wA3 = cA.w * nA.w;
    const float wB0 = cB.x * nB.x, wB1 = cB.y * nB.y, wB2 = cB.z * nB.z, wB3 = cB.w * nB.w;

    const float sA = (wA0 + wA1) + (wA2 + wA3);
    const float sB = (wB0 + wB1) + (wB2 + wB3);

    // Two interleaved Kogge-Stone inclusive scans (independent chains overlap).
    float vA = sA, vB = sB;
#pragma unroll
    for (int off = 1; off < 32; off <<= 1) {
        float uA = __shfl_up_sync(0xffffffffu, vA, off);
        float uB = __shfl_up_sync(0xffffffffu, vB, off);
        if (lane >= off) { vA += uA; vB += uB; }
    }
    const float exclA = vA - sA;
    const float totA  = __shfl_sync(0xffffffffu, vA, 31);
    const float exclB = totA + vB - sB;

    // y_k = prefix_k + d_k*n_k ;  logit_k = sb*y_k - beta + (k==x)*beta*K
    const float bonus = beta * (float)KC;
    float lg[8];
    {
        float p = exclA;
        const int k = 4 * lane;
        lg[0] = fmaf(sb, p + dA.x * nA.x, -beta) + ((k + 0 == x) ? bonus : 0.0f); p += wA0;
        lg[1] = fmaf(sb, p + dA.y * nA.y, -beta) + ((k + 1 == x) ? bonus : 0.0f); p += wA1;
        lg[2] = fmaf(sb, p + dA.z * nA.z, -beta) + ((k + 2 == x) ? bonus : 0.0f); p += wA2;
        lg[3] = fmaf(sb, p + dA.w * nA.w, -beta) + ((k + 3 == x) ? bonus : 0.0f);
    }
    {
        float p = exclB;
        const int k = 128 + 4 * lane;
        lg[4] = fmaf(sb, p + dB.x * nB.x, -beta) + ((k + 0 == x) ? bonus : 0.0f); p += wB0;
        lg[5] = fmaf(sb, p + dB.y * nB.y, -beta) + ((k + 1 == x) ? bonus : 0.0f); p += wB1;
        lg[6] = fmaf(sb, p + dB.z * nB.z, -beta) + ((k + 2 == x) ? bonus : 0.0f); p += wB2;
        lg[7] = fmaf(sb, p + dB.w * nB.w, -beta) + ((k + 3 == x) ? bonus : 0.0f);
    }

    // Warp-wide softmax over the 256 logits.
    float m = fmaxf(fmaxf(fmaxf(lg[0], lg[1]), fmaxf(lg[2], lg[3])),
                    fmaxf(fmaxf(lg[4], lg[5]), fmaxf(lg[6], lg[7])));
    m = warp_max(m);

    float e[8];
    float s = 0.0f;
#pragma unroll
    for (int i = 0; i < 8; i++) { e[i] = __expf(lg[i] - m); s += e[i]; }
    s = warp_sum(s);
    const float inv = __frcp_rn(s);

    float4 oA, oB;
    if (lo) {                                  // warp-uniform branch
        const float uni = 1.0f / (float)KC;
        oA = make_float4(uni, uni, uni, uni);
        oB = oA;
    } else {
        oA = make_float4(e[0] * inv, e[1] * inv, e[2] * inv, e[3] * inv);
        oB = make_float4(e[4] * inv, e[5] * inv, e[6] * inv, e[7] * inv);
    }

    float4* orow = (float4*)(out + (size_t)row * KC);
    orow[lane]      = oA;
    orow[32 + lane] = oB;
}

extern "C" void kernel_launch(void* const* d_in, const int* in_sizes, int n_in,
                              void* d_out, int out_size)
{
    const int*   data  = (const int*)  d_in[0];   // [B,S] int32 class indices
    const float* t     = (const float*)d_in[1];   // [B,S] float32
    const float* noise = (const float*)d_in[2];   // [B,S,K] float32
    float*       out   = (float*)d_out;           // [B,S,K] float32

    const int n_rows = in_sizes[0];               // B*S
    const int blocks = (n_rows + ROWS_PER_BLOCK - 1) / ROWS_PER_BLOCK;
    dbf_kernel<<<blocks, NTHREADS>>>(data, t, noise, out, n_rows);
}